// round 12
// baseline (speedup 1.0000x reference)
#include <cuda_runtime.h>
#include <cstddef>

// Problem constants (fixed by the dataset)
#define Fk   51
#define HOo  512
#define WOo  512
#define CC   3
#define HIN  562   // HO + F - 1
#define WIN  562
#define BB   2
#define HW   (HOo * WOo)

// Tiling: each thread computes 2 x-cols x 2 y-rows. Block = 32x10 threads
// -> output tile 64 wide x 20 tall. ALL 3 channels resident in smem.
// 2 CTAs/SM = 20 warps/SM (reg cap ~96-102/thread, smem 2*95.8KB < 228KB).
#define TXX  32
#define WYY  10
#define RXX  2
#define RYY  2
#define TW   (TXX * RXX)        // 64 output cols per block
#define TYY  (WYY * RYY)        // 20 output rows per block (512 = 25.6 blocks -> clamp)
#define NTHREADS (TXX * WYY)    // 320
#define TROWS (TYY + Fk - 1)    // 70 input rows
#define TCOLS 114               // cols 0..113 used (2*31 + 51 = 113); even stride
#define TILE_ELEMS (TROWS * TCOLS)     // 7980
#define SMEM_FLOATS (CC * TILE_ELEMS)  // 23940 -> 95760 bytes

typedef unsigned long long u64;

// ---- packed f32x2 helpers (Blackwell FFMA2 path) ----
__device__ __forceinline__ u64 pack2(float lo, float hi) {
    u64 r;
    asm("mov.b64 %0, {%1, %2};" : "=l"(r) : "f"(lo), "f"(hi));
    return r;
}
__device__ __forceinline__ void unpack2(u64 v, float& lo, float& hi) {
    asm("mov.b64 {%0, %1}, %2;" : "=f"(lo), "=f"(hi) : "l"(v));
}
__device__ __forceinline__ void ffma2(u64& d, u64 a, u64 b) {
    asm("fma.rn.f32x2 %0, %1, %2, %0;" : "+l"(d) : "l"(a), "l"(b));
}
__device__ __forceinline__ float2 ldg2(const float* p) {
    return __ldg(reinterpret_cast<const float2*>(p));
}

// Process one group of P tap-pairs (pairs T0 .. T0+P-1).
// Live registers: 4*P u64 for h + 4 u64 s (scoped per channel) -> fits ~96-reg cap.
template<int P>
__device__ __forceinline__ void process_group(
    int T0,
    const float* __restrict__ h_base,
    const float* __restrict__ v_base,
    const float* __restrict__ tile,
    int rowoff,
    u64 (&acc)[CC][RXX][RYY])
{
    // col A (x=xA):   pair T -> {h[2T],   h[2T+1]}  (h[51] := 0)
    // col B (x=xA+1): pair T -> {h[2T-1], h[2T]}    (h[-1] := 0)
    u64 hA2[RYY][P], hB2[RYY][P];
    #pragma unroll
    for (int yy = 0; yy < RYY; ++yy) {
        const float* hp = h_base + (size_t)yy * WOo;
        #pragma unroll
        for (int tl = 0; tl < P; ++tl) {
            int T = T0 + tl;
            float2 gm = (2 * T - 1 >= 0) ? ldg2(hp + (size_t)(2 * T - 1) * HW)
                                         : make_float2(0.f, 0.f);
            float2 gc = ldg2(hp + (size_t)(2 * T) * HW);       // 2T <= 50 always
            float2 gp = (2 * T + 1 < Fk) ? ldg2(hp + (size_t)(2 * T + 1) * HW)
                                         : make_float2(0.f, 0.f);
            hA2[yy][tl] = pack2(gc.x, gp.x);
            hB2[yy][tl] = pack2(gm.y, gc.y);
        }
    }

    const float* base = tile + rowoff + 2 * T0;

    #pragma unroll 1
    for (int rr = 0; rr < Fk + RYY - 1; ++rr) {   // 52 input rows
        // vertical weights for both columns; issued early, consumed per channel
        float2 v0 = (rr <= Fk - 1) ? ldg2(v_base + (size_t)rr * HW)
                                   : make_float2(0.f, 0.f);
        float2 v1 = (rr >= 1)      ? ldg2(v_base + (size_t)(rr - 1) * HW + WOo)
                                   : make_float2(0.f, 0.f);
        u64 v0x = pack2(v0.x, v0.x), v1x = pack2(v1.x, v1.x);
        u64 v0y = pack2(v0.y, v0.y), v1y = pack2(v1.y, v1.y);

        // Per channel: 4 packed dot-product chains, v applied immediately
        // (s scoped here -> only 4 u64 live, frees 16 regs vs batched apply)
        #pragma unroll
        for (int c = 0; c < CC; ++c) {
            u64 s0 = 0ULL, s1 = 0ULL, s2 = 0ULL, s3 = 0ULL;
            const u64* rp = reinterpret_cast<const u64*>(
                base + c * TILE_ELEMS + rr * TCOLS);
            #pragma unroll
            for (int tl = 0; tl < P; ++tl) {
                u64 ip = rp[tl];                 // aligned LDS.64
                ffma2(s0, ip, hA2[0][tl]);
                ffma2(s1, ip, hA2[1][tl]);
                ffma2(s2, ip, hB2[0][tl]);
                ffma2(s3, ip, hB2[1][tl]);
            }
            ffma2(acc[c][0][0], v0x, s0);
            ffma2(acc[c][0][1], v1x, s1);
            ffma2(acc[c][1][0], v0y, s2);
            ffma2(acc[c][1][1], v1y, s3);
        }
    }
}

__global__ __launch_bounds__(NTHREADS, 2)
void sepconv_kernel(const float* __restrict__ inp,
                    const float* __restrict__ vert,
                    const float* __restrict__ horz,
                    float* __restrict__ out)
{
    extern __shared__ float tile[];   // [CC][TROWS][TCOLS]

    const int b   = blockIdx.z;
    const int x0  = blockIdx.x * TW;
    const int y0  = blockIdx.y * TYY;
    const int tx  = threadIdx.x;
    const int ty  = threadIdx.y;
    const int tid = ty * TXX + tx;

    const int xA = x0 + 2 * tx;      // thread's even column (and xA+1)
    int yA = y0 + ty * RYY;          // nominal rows yA, yA+1
    if (yA > HOo - RYY) yA = HOo - RYY;   // ragged-edge clamp (duplicate work, benign)

    // filter bases: layout [b, tap, y, x]
    const float* h_base = horz + (size_t)b * Fk * HW + (size_t)yA * WOo + xA;
    const float* v_base = vert + (size_t)b * Fk * HW + (size_t)yA * WOo + xA;

    // ---- Load ALL 3 channel tiles once (row-clamped for the last y-block) ----
    {
        const float* gsrc = inp + ((size_t)b * CC * HIN) * WIN + x0;
        #pragma unroll 1
        for (int idx = tid; idx < SMEM_FLOATS; idx += NTHREADS) {
            int c   = idx / TILE_ELEMS;
            int rem = idx - c * TILE_ELEMS;
            int r   = rem / TCOLS;
            int col = rem - r * TCOLS;
            int gr  = y0 + r; if (gr > HIN - 1) gr = HIN - 1;   // clamped rows never read
            tile[idx] = gsrc[((size_t)c * HIN + gr) * WIN + col];
        }
    }
    __syncthreads();

    // accumulators: [channel][col A/B][row yy], packed {even-chain, odd-chain}
    u64 acc[CC][RXX][RYY];
    #pragma unroll
    for (int c = 0; c < CC; ++c)
        #pragma unroll
        for (int cx = 0; cx < RXX; ++cx)
            #pragma unroll
            for (int yy = 0; yy < RYY; ++yy) acc[c][cx][yy] = 0ULL;

    const int rowoff = (yA - y0) * TCOLS + 2 * tx;

    // 26 tap pairs (taps 0..51, h[51]:=0) in 7 register-bounded groups
    process_group<4>( 0, h_base, v_base, tile, rowoff, acc);
    process_group<4>( 4, h_base, v_base, tile, rowoff, acc);
    process_group<4>( 8, h_base, v_base, tile, rowoff, acc);
    process_group<4>(12, h_base, v_base, tile, rowoff, acc);
    process_group<4>(16, h_base, v_base, tile, rowoff, acc);
    process_group<4>(20, h_base, v_base, tile, rowoff, acc);
    process_group<2>(24, h_base, v_base, tile, rowoff, acc);

    // ---- Epilogue: horizontal add of packed partials, coalesced STG.64 ----
    #pragma unroll
    for (int c = 0; c < CC; ++c) {
        float* op = out + (((size_t)b * CC + c) * HOo + yA) * WOo + xA;
        #pragma unroll
        for (int yy = 0; yy < RYY; ++yy) {
            float aLo, aHi, bLo, bHi;
            unpack2(acc[c][0][yy], aLo, aHi);
            unpack2(acc[c][1][yy], bLo, bHi);
            *reinterpret_cast<float2*>(op + (size_t)yy * WOo)
                = make_float2(aLo + aHi, bLo + bHi);
        }
    }
}

extern "C" void kernel_launch(void* const* d_in, const int* in_sizes, int n_in,
                              void* d_out, int out_size)
{
    // Identify 'input' by element count; keep relative order of vertical/horizontal.
    const int input_elems = BB * CC * HIN * WIN;   // 1,895,064
    int idx_in = 0;
    for (int i = 0; i < n_in; ++i)
        if (in_sizes[i] == input_elems) { idx_in = i; break; }
    int idx_v = -1, idx_h = -1;
    for (int i = 0; i < n_in; ++i) {
        if (i == idx_in) continue;
        if (idx_v < 0) idx_v = i; else if (idx_h < 0) idx_h = i;
    }

    const float* inp  = (const float*)d_in[idx_in];
    const float* vert = (const float*)d_in[idx_v];
    const float* horz = (const float*)d_in[idx_h];
    float* o = (float*)d_out;

    const int smem_bytes = SMEM_FLOATS * (int)sizeof(float);   // 95760
    cudaFuncSetAttribute(sepconv_kernel,
                         cudaFuncAttributeMaxDynamicSharedMemorySize, smem_bytes);

    dim3 block(TXX, WYY, 1);
    dim3 grid(WOo / TW, (HOo + TYY - 1) / TYY, BB);   // (8, 26, 2) = 416 blocks
    sepconv_kernel<<<grid, block, smem_bytes>>>(inp, vert, horz, o);
}

// round 13
// speedup vs baseline: 1.0600x; 1.0600x over previous
#include <cuda_runtime.h>
#include <cstddef>

// Problem constants (fixed by the dataset)
#define Fk   51
#define HOo  512
#define WOo  512
#define CC   3
#define HIN  562   // HO + F - 1
#define WIN  562
#define BB   2
#define HW   (HOo * WOo)

// Tiling (R11 geometry — best measured): 2 x-cols x 2 y-rows per thread,
// block 32x8=256 threads -> 64x16 output tile, 3 channels in smem,
// 2 CTAs/SM = 16 warps/SM.
#define TXX  32
#define WYY  8
#define RXX  2
#define RYY  2
#define TW   (TXX * RXX)        // 64
#define TYY  (WYY * RYY)        // 16 (512 % 16 == 0, no ragged edge)
#define NTHREADS (TXX * WYY)    // 256
#define TROWS (TYY + Fk - 1)    // 66
#define TCOLS 114
#define TILE_ELEMS (TROWS * TCOLS)     // 7524
#define SMEM_FLOATS (CC * TILE_ELEMS)  // 22572 -> 90288 bytes

typedef unsigned long long u64;

// ---- packed f32x2 helpers (Blackwell FFMA2 path) ----
__device__ __forceinline__ u64 pack2(float lo, float hi) {
    u64 r;
    asm("mov.b64 %0, {%1, %2};" : "=l"(r) : "f"(lo), "f"(hi));
    return r;
}
__device__ __forceinline__ void unpack2(u64 v, float& lo, float& hi) {
    asm("mov.b64 {%0, %1}, %2;" : "=f"(lo), "=f"(hi) : "l"(v));
}
__device__ __forceinline__ void ffma2(u64& d, u64 a, u64 b) {
    asm("fma.rn.f32x2 %0, %1, %2, %0;" : "+l"(d) : "l"(a), "l"(b));
}
__device__ __forceinline__ u64 mul2(u64 a, u64 b) {
    u64 r;
    asm("mul.rn.f32x2 %0, %1, %2;" : "=l"(r) : "l"(a), "l"(b));
    return r;
}
__device__ __forceinline__ float2 ldg2(const float* p) {
    return __ldg(reinterpret_cast<const float2*>(p));
}

// Process one group of P tap-pairs (pairs T0 .. T0+P-1).
template<int P>
__device__ __forceinline__ void process_group(
    int T0,
    const float* __restrict__ h_base,
    const float* __restrict__ v_base,
    const float* __restrict__ tile,
    int rowoff,
    u64 (&acc)[CC][RXX][RYY])
{
    // col A (x=xA):   pair T -> {h[2T],   h[2T+1]}  (h[51] := 0)
    // col B (x=xA+1): pair T -> {h[2T-1], h[2T]}    (h[-1] := 0)
    u64 hA2[RYY][P], hB2[RYY][P];
    #pragma unroll
    for (int yy = 0; yy < RYY; ++yy) {
        const float* hp = h_base + (size_t)yy * WOo;
        #pragma unroll
        for (int tl = 0; tl < P; ++tl) {
            int T = T0 + tl;
            float2 gm = (2 * T - 1 >= 0) ? ldg2(hp + (size_t)(2 * T - 1) * HW)
                                         : make_float2(0.f, 0.f);
            float2 gc = ldg2(hp + (size_t)(2 * T) * HW);       // 2T <= 50 always
            float2 gp = (2 * T + 1 < Fk) ? ldg2(hp + (size_t)(2 * T + 1) * HW)
                                         : make_float2(0.f, 0.f);
            hA2[yy][tl] = pack2(gc.x, gp.x);
            hB2[yy][tl] = pack2(gm.y, gc.y);
        }
    }

    const float* base = tile + rowoff + 2 * T0;

    // ---- Peeled rr = 0: only yy=0 output rows receive this input row ----
    {
        float2 v0 = ldg2(v_base);                       // i = 0
        u64 v0x = pack2(v0.x, v0.x), v0y = pack2(v0.y, v0.y);
        #pragma unroll
        for (int c = 0; c < CC; ++c) {
            const u64* rp = reinterpret_cast<const u64*>(base + c * TILE_ELEMS);
            u64 ip = rp[0];
            u64 s0 = mul2(ip, hA2[0][0]);
            u64 s2 = mul2(ip, hB2[0][0]);
            #pragma unroll
            for (int tl = 1; tl < P; ++tl) {
                ip = rp[tl];
                ffma2(s0, ip, hA2[0][tl]);
                ffma2(s2, ip, hB2[0][tl]);
            }
            ffma2(acc[c][0][0], v0x, s0);
            ffma2(acc[c][1][0], v0y, s2);
        }
    }

    // ---- Body rr = 1..50: unpredicated, v software-pipelined one iter ahead ----
    float2 v0 = ldg2(v_base + (size_t)1 * HW);          // v[i=1]   for rr=1
    float2 v1 = ldg2(v_base + WOo);                      // v[i=0,y+1] for rr=1
    #pragma unroll 1
    for (int rr = 1; rr <= Fk - 1; ++rr) {               // 1..50
        // prefetch next iteration's v (full loop body of latency cover)
        int nrr = (rr + 1 <= Fk - 1) ? rr + 1 : Fk - 1;  // clamp keeps load in-bounds
        float2 nv0 = ldg2(v_base + (size_t)nrr * HW);
        float2 nv1 = ldg2(v_base + (size_t)rr * HW + WOo);

        u64 v0x = pack2(v0.x, v0.x), v1x = pack2(v1.x, v1.x);
        u64 v0y = pack2(v0.y, v0.y), v1y = pack2(v1.y, v1.y);

        #pragma unroll
        for (int c = 0; c < CC; ++c) {
            const u64* rp = reinterpret_cast<const u64*>(
                base + c * TILE_ELEMS + rr * TCOLS);
            u64 ip = rp[0];
            u64 s0 = mul2(ip, hA2[0][0]);                // first tap: mul (no zero-init)
            u64 s1 = mul2(ip, hA2[1][0]);
            u64 s2 = mul2(ip, hB2[0][0]);
            u64 s3 = mul2(ip, hB2[1][0]);
            #pragma unroll
            for (int tl = 1; tl < P; ++tl) {
                ip = rp[tl];
                ffma2(s0, ip, hA2[0][tl]);
                ffma2(s1, ip, hA2[1][tl]);
                ffma2(s2, ip, hB2[0][tl]);
                ffma2(s3, ip, hB2[1][tl]);
            }
            ffma2(acc[c][0][0], v0x, s0);
            ffma2(acc[c][0][1], v1x, s1);
            ffma2(acc[c][1][0], v0y, s2);
            ffma2(acc[c][1][1], v1y, s3);
        }
        v0 = nv0; v1 = nv1;
    }

    // ---- Peeled rr = 51: only yy=1 output rows (v1 = v[i=50,y+1], prefetched) ----
    {
        u64 v1x = pack2(v1.x, v1.x), v1y = pack2(v1.y, v1.y);
        #pragma unroll
        for (int c = 0; c < CC; ++c) {
            const u64* rp = reinterpret_cast<const u64*>(
                base + c * TILE_ELEMS + (Fk + RYY - 2) * TCOLS);
            u64 ip = rp[0];
            u64 s1 = mul2(ip, hA2[1][0]);
            u64 s3 = mul2(ip, hB2[1][0]);
            #pragma unroll
            for (int tl = 1; tl < P; ++tl) {
                ip = rp[tl];
                ffma2(s1, ip, hA2[1][tl]);
                ffma2(s3, ip, hB2[1][tl]);
            }
            ffma2(acc[c][0][1], v1x, s1);
            ffma2(acc[c][1][1], v1y, s3);
        }
    }
}

__global__ __launch_bounds__(NTHREADS, 2)
void sepconv_kernel(const float* __restrict__ inp,
                    const float* __restrict__ vert,
                    const float* __restrict__ horz,
                    float* __restrict__ out)
{
    extern __shared__ float tile[];   // [CC][TROWS][TCOLS]

    const int b   = blockIdx.z;
    const int x0  = blockIdx.x * TW;
    const int y0  = blockIdx.y * TYY;
    const int tx  = threadIdx.x;
    const int ty  = threadIdx.y;
    const int tid = ty * TXX + tx;

    const int xA = x0 + 2 * tx;      // thread's even column (and xA+1)
    const int yA = y0 + ty * RYY;    // thread's rows yA, yA+1

    // filter bases: layout [b, tap, y, x]
    const float* h_base = horz + (size_t)b * Fk * HW + (size_t)yA * WOo + xA;
    const float* v_base = vert + (size_t)b * Fk * HW + (size_t)yA * WOo + xA;

    // ---- Load ALL 3 channel tiles once (fully in-bounds) ----
    {
        const float* gsrc = inp + ((size_t)b * CC * HIN + y0) * WIN + x0;
        #pragma unroll 1
        for (int idx = tid; idx < SMEM_FLOATS; idx += NTHREADS) {
            int c   = idx / TILE_ELEMS;
            int rem = idx - c * TILE_ELEMS;
            int r   = rem / TCOLS;
            int col = rem - r * TCOLS;
            tile[idx] = gsrc[((size_t)c * HIN + r) * WIN + col];
        }
    }
    __syncthreads();

    // accumulators: [channel][col A/B][row yy], packed {even-chain, odd-chain}
    u64 acc[CC][RXX][RYY];
    #pragma unroll
    for (int c = 0; c < CC; ++c)
        #pragma unroll
        for (int cx = 0; cx < RXX; ++cx)
            #pragma unroll
            for (int yy = 0; yy < RYY; ++yy) acc[c][cx][yy] = 0ULL;

    const int rowoff = (ty * RYY) * TCOLS + 2 * tx;

    // 26 tap pairs (taps 0..51, h[51]:=0) in 4 register-bounded groups
    process_group<7>( 0, h_base, v_base, tile, rowoff, acc);
    process_group<7>( 7, h_base, v_base, tile, rowoff, acc);
    process_group<7>(14, h_base, v_base, tile, rowoff, acc);
    process_group<5>(21, h_base, v_base, tile, rowoff, acc);

    // ---- Epilogue: horizontal add of packed partials, coalesced STG.64 ----
    #pragma unroll
    for (int c = 0; c < CC; ++c) {
        float* op = out + (((size_t)b * CC + c) * HOo + yA) * WOo + xA;
        #pragma unroll
        for (int yy = 0; yy < RYY; ++yy) {
            float aLo, aHi, bLo, bHi;
            unpack2(acc[c][0][yy], aLo, aHi);
            unpack2(acc[c][1][yy], bLo, bHi);
            *reinterpret_cast<float2*>(op + (size_t)yy * WOo)
                = make_float2(aLo + aHi, bLo + bHi);
        }
    }
}

extern "C" void kernel_launch(void* const* d_in, const int* in_sizes, int n_in,
                              void* d_out, int out_size)
{
    // Identify 'input' by element count; keep relative order of vertical/horizontal.
    const int input_elems = BB * CC * HIN * WIN;   // 1,895,064
    int idx_in = 0;
    for (int i = 0; i < n_in; ++i)
        if (in_sizes[i] == input_elems) { idx_in = i; break; }
    int idx_v = -1, idx_h = -1;
    for (int i = 0; i < n_in; ++i) {
        if (i == idx_in) continue;
        if (idx_v < 0) idx_v = i; else if (idx_h < 0) idx_h = i;
    }

    const float* inp  = (const float*)d_in[idx_in];
    const float* vert = (const float*)d_in[idx_v];
    const float* horz = (const float*)d_in[idx_h];
    float* o = (float*)d_out;

    const int smem_bytes = SMEM_FLOATS * (int)sizeof(float);   // 90288
    cudaFuncSetAttribute(sepconv_kernel,
                         cudaFuncAttributeMaxDynamicSharedMemorySize, smem_bytes);

    dim3 block(TXX, WYY, 1);
    dim3 grid(WOo / TW, HOo / TYY, BB);   // (8, 32, 2) = 512 blocks
    sepconv_kernel<<<grid, block, smem_bytes>>>(inp, vert, horz, o);
}